// round 3
// baseline (speedup 1.0000x reference)
#include <cuda_runtime.h>
#include <cstdint>

// Problem constants
#define L_DIM   32
#define BEAM    8
#define KV2     2
#define HEADS   8
#define SEQ     1024
#define HDIM    64
#define VOCAB   50257
#define HIST    128
#define TOPK    8

// kv_cache elements = 32*8*2*8*1024*64 = 268,435,456 floats
#define KV_ELEMS      268435456ULL
// floats per (layer, beam) slab = 2*8*1024*64 = 1,048,576 -> 262,144 float4
#define SLAB_F4       262144
#define SLAB_F4_SHIFT 18

#define NEG_INF (__int_as_float(0xff800000))
#define IDX_MAX 0x7fffffff

// cross-kernel scratch (allocation-free: __device__ globals)
__device__ float g_lse[BEAM];
__device__ float g_topv[BEAM][TOPK];
__device__ int   g_topi[BEAM][TOPK];
__device__ int   g_beam_index[BEAM];

// ---------------------------------------------------------------------------
// Kernel 1: per-beam-row logsumexp + top-8 of logits.
// grid = BEAM blocks, 256 threads.
// ---------------------------------------------------------------------------
__global__ void __launch_bounds__(256) k_row_topk(const float* __restrict__ logits)
{
    const int row = blockIdx.x;
    const float* __restrict__ x = logits + (size_t)row * VOCAB;
    const int t = threadIdx.x;
    const unsigned F = 0xffffffffu;

    // online LSE accumulators + local sorted top-8
    float m = NEG_INF, s = 0.0f;
    float lv[TOPK]; int li[TOPK];
#pragma unroll
    for (int j = 0; j < TOPK; j++) { lv[j] = NEG_INF; li[j] = IDX_MAX; }

    for (int i = t; i < VOCAB; i += 256) {
        float v = x[i];
        // stable online logsumexp
        if (v > m) { s = s * expf(m - v) + 1.0f; m = v; }
        else       { s += expf(v - m); }
        // insert into sorted-descending local top-8 (tie: smaller index first)
        if (v > lv[TOPK - 1] || (v == lv[TOPK - 1] && i < li[TOPK - 1])) {
            int j = TOPK - 1;
            while (j > 0 && (v > lv[j - 1] || (v == lv[j - 1] && i < li[j - 1]))) {
                lv[j] = lv[j - 1]; li[j] = li[j - 1]; j--;
            }
            lv[j] = v; li[j] = i;
        }
    }

    // warp-level LSE reduction (every thread saw >=196 elements, m is finite)
    for (int off = 16; off; off >>= 1) {
        float om = __shfl_down_sync(F, m, off);
        float os = __shfl_down_sync(F, s, off);
        if (om > m) { s = s * expf(m - om) + os; m = om; }
        else        { s = s + os * expf(om - m); }
    }

    __shared__ float sm_m[8], sm_s[8];
    __shared__ float cv[2048];
    __shared__ int   ci[2048];

    const int wid = t >> 5, lane = t & 31;
    if (lane == 0) { sm_m[wid] = m; sm_s[wid] = s; }
#pragma unroll
    for (int j = 0; j < TOPK; j++) { cv[t * TOPK + j] = lv[j]; ci[t * TOPK + j] = li[j]; }
    __syncthreads();

    if (t == 0) {
        float M = sm_m[0], S = sm_s[0];
#pragma unroll
        for (int w = 1; w < 8; w++) {
            float om = sm_m[w], os = sm_s[w];
            if (om > M) { S = S * expf(M - om) + os; M = om; }
            else        { S += os * expf(om - M); }
        }
        g_lse[row] = M + logf(S);
    }

    // warp 0: merge 2048 candidates -> global top-8 (sorted desc, tie by index)
    if (t < 32) {
        float bv[TOPK]; int bi[TOPK];
#pragma unroll
        for (int j = 0; j < TOPK; j++) { bv[j] = NEG_INF; bi[j] = IDX_MAX; }
        const int base = t * 64;
        for (int k = 0; k < 64; k++) {
            float v = cv[base + k]; int idx = ci[base + k];
            if (v > bv[TOPK - 1] || (v == bv[TOPK - 1] && idx < bi[TOPK - 1])) {
                int j = TOPK - 1;
                while (j > 0 && (v > bv[j - 1] || (v == bv[j - 1] && idx < bi[j - 1]))) {
                    bv[j] = bv[j - 1]; bi[j] = bi[j - 1]; j--;
                }
                bv[j] = v; bi[j] = idx;
            }
        }
        // 8 rounds of warp argmax-remove over each lane's sorted head
        int ptr = 0;
#pragma unroll
        for (int r = 0; r < TOPK; r++) {
            float rv = (ptr < TOPK) ? bv[ptr] : NEG_INF;
            int   ri = (ptr < TOPK) ? bi[ptr] : IDX_MAX;
            int   rl = t;
            for (int off = 16; off; off >>= 1) {
                float ov = __shfl_down_sync(F, rv, off);
                int   oi = __shfl_down_sync(F, ri, off);
                int   ol = __shfl_down_sync(F, rl, off);
                if (ov > rv || (ov == rv && oi < ri)) { rv = ov; ri = oi; rl = ol; }
            }
            rv = __shfl_sync(F, rv, 0);
            ri = __shfl_sync(F, ri, 0);
            rl = __shfl_sync(F, rl, 0);
            if (t == rl) ptr++;
            if (t == 0) { g_topv[row][r] = rv; g_topi[row][r] = ri; }
        }
    }
}

// ---------------------------------------------------------------------------
// Kernel 2: beam selection (top-8 of 64 candidates) + all small outputs.
// 1 block, 32 threads.
// ---------------------------------------------------------------------------
__global__ void k_select(const float* __restrict__ prev,
                         const int*   __restrict__ save_id,
                         float*       __restrict__ out)
{
    const int lane = threadIdx.x;
    const unsigned F = 0xffffffffu;
    __shared__ int   s_beam[BEAM];
    __shared__ int   s_tok[BEAM];
    __shared__ float s_prob[BEAM];

    // two candidates per lane: flat indices lane and lane+32
    const int f0 = lane, f1 = lane + 32;
    float v0 = g_topv[f0 >> 3][f0 & 7] - g_lse[f0 >> 3] + prev[f0 >> 3];
    float v1 = g_topv[f1 >> 3][f1 & 7] - g_lse[f1 >> 3] + prev[f1 >> 3];
    float c0v, c1v; int c0i, c1i;
    if (v1 > v0) { c0v = v1; c0i = f1; c1v = v0; c1i = f0; }   // tie keeps f0 first (f0 < f1)
    else         { c0v = v0; c0i = f0; c1v = v1; c1i = f1; }

    int ptr = 0;
#pragma unroll
    for (int r = 0; r < BEAM; r++) {
        float rv; int ri;
        if      (ptr == 0) { rv = c0v; ri = c0i; }
        else if (ptr == 1) { rv = c1v; ri = c1i; }
        else               { rv = NEG_INF; ri = IDX_MAX; }
        int rl = lane;
        for (int off = 16; off; off >>= 1) {
            float ov = __shfl_down_sync(F, rv, off);
            int   oi = __shfl_down_sync(F, ri, off);
            int   ol = __shfl_down_sync(F, rl, off);
            if (ov > rv || (ov == rv && oi < ri)) { rv = ov; ri = oi; rl = ol; }
        }
        rv = __shfl_sync(F, rv, 0);
        ri = __shfl_sync(F, ri, 0);
        rl = __shfl_sync(F, rl, 0);
        if (lane == rl) ptr++;
        if (lane == 0) {
            const int beam = ri >> 3;
            s_beam[r] = beam;
            s_tok[r]  = g_topi[beam][ri & 7];
            s_prob[r] = rv;
        }
    }
    __syncwarp();

    const size_t OFF = KV_ELEMS;
    // new_save_id: (8, 129) = gathered save_id rows + new token
    for (int e = lane; e < BEAM * (HIST + 1); e += 32) {
        const int r = e / (HIST + 1), c = e % (HIST + 1);
        const float val = (c < HIST) ? (float)save_id[s_beam[r] * HIST + c]
                                     : (float)s_tok[r];
        out[OFF + e] = val;
    }
    if (lane < BEAM) {
        out[OFF + 1032 + lane] = s_prob[lane];          // top_beam_prob (8,1)
        out[OFF + 1040 + lane] = (float)s_tok[lane];    // tbi (8,1)
        g_beam_index[lane] = s_beam[lane];
    }
    if (lane == 0)
        out[OFF + 1048] = (float)s_tok[0];              // max_logits_idx (1,1)
}

// ---------------------------------------------------------------------------
// Kernel 3: kv_cache gather (the 2 GiB streaming copy).
// 256 (l,b) slabs, each 262,144 float4; 64 blocks per slab, 256 threads,
// 16 independent float4 loads per thread for MLP depth.
// grid = 256*64 = 16384 blocks.
// ---------------------------------------------------------------------------
__global__ void __launch_bounds__(256) k_gather(const float4* __restrict__ src,
                                                float4*       __restrict__ dst)
{
    const int slab  = blockIdx.x >> 6;   // 0..255 = l*8 + b
    const int chunk = blockIdx.x & 63;
    const int b     = slab & 7;
    const int l     = slab >> 3;
    const int src_slab = (l << 3) | g_beam_index[b];

    const size_t out_base = ((size_t)slab     << SLAB_F4_SHIFT) + ((size_t)chunk << 12);
    const size_t in_base  = ((size_t)src_slab << SLAB_F4_SHIFT) + ((size_t)chunk << 12);

#pragma unroll
    for (int k = 0; k < 16; k++) {
        const int off = threadIdx.x + k * 256;
        dst[out_base + off] = src[in_base + off];
    }
}

// ---------------------------------------------------------------------------
extern "C" void kernel_launch(void* const* d_in, const int* in_sizes, int n_in,
                              void* d_out, int out_size)
{
    const float* kv      = (const float*)d_in[0];
    const float* logits  = (const float*)d_in[1];
    const int*   save_id = (const int*)  d_in[2];
    const float* prev    = (const float*)d_in[3];
    float* out = (float*)d_out;

    k_row_topk<<<BEAM, 256>>>(logits);
    k_select<<<1, 32>>>(prev, save_id, out);
    k_gather<<<16384, 256>>>((const float4*)kv, (float4*)out);
}

// round 4
// speedup vs baseline: 1.6752x; 1.6752x over previous
#include <cuda_runtime.h>
#include <cstdint>

// Problem constants
#define L_DIM   32
#define BEAM    8
#define KV2     2
#define HEADS   8
#define SEQ     1024
#define HDIM    64
#define VOCAB   50257
#define HIST    128
#define TOPK    8

#define KV_ELEMS      268435456ULL     // 32*8*2*8*1024*64
#define SLAB_F4_SHIFT 18               // 262,144 float4 per (layer,beam) slab

#define BLKS_PER_ROW  8
#define BLOCK_ELEMS   6400             // 8*6400 = 51200 >= 50257

#define NEG_INF (__int_as_float(0xff800000))
#define IDX_MAX 0x7fffffff

// cross-kernel scratch
__device__ float g_blk_m[BEAM][BLKS_PER_ROW];
__device__ float g_blk_s[BEAM][BLKS_PER_ROW];
__device__ float g_blk_topv[BEAM][BLKS_PER_ROW * TOPK];
__device__ int   g_blk_topi[BEAM][BLKS_PER_ROW * TOPK];
__device__ int   g_beam_index[BEAM];

// sorted-descending insert, all static indices (stays in registers)
__device__ __forceinline__ void top8_insert(float v, int idx, float lv[TOPK], int li[TOPK])
{
    if (v > lv[TOPK - 1] || (v == lv[TOPK - 1] && idx < li[TOPK - 1])) {
        float cv = v; int ci = idx;
#pragma unroll
        for (int j = 0; j < TOPK; j++) {
            bool gt = (cv > lv[j]) || (cv == lv[j] && ci < li[j]);
            float tv = lv[j]; int ti = li[j];
            if (gt) { lv[j] = cv; li[j] = ci; cv = tv; ci = ti; }
        }
    }
}

// full-warp argmax-remove over per-lane sorted lists -> 8 winners (desc, tie: smaller idx).
// Every lane converges (xor butterfly). Winner stored by lane 0 into out arrays.
__device__ __forceinline__ void warp_top8_merge(float lv[TOPK], int li[TOPK],
                                                int depth,       // valid entries per lane
                                                float* out_v, int* out_i)
{
    const unsigned F = 0xffffffffu;
    const int lane = threadIdx.x & 31;
    int ptr = 0;
#pragma unroll
    for (int r = 0; r < TOPK; r++) {
        float rv = NEG_INF; int ri = IDX_MAX;
#pragma unroll
        for (int j = 0; j < TOPK; j++)            // static-index select of lv[ptr]
            if (j == ptr && j < depth) { rv = lv[j]; ri = li[j]; }
        int rl = lane;
        for (int off = 16; off; off >>= 1) {
            float ov = __shfl_xor_sync(F, rv, off);
            int   oi = __shfl_xor_sync(F, ri, off);
            int   ol = __shfl_xor_sync(F, rl, off);
            if (ov > rv || (ov == rv && oi < ri)) { rv = ov; ri = oi; rl = ol; }
        }
        if (lane == rl) ptr++;
        if (lane == 0) { out_v[r] = rv; out_i[r] = ri; }
    }
}

// ---------------------------------------------------------------------------
// Kernel 1: partial LSE + partial top-8. grid = 8 rows x 8 blocks, 256 thr.
// ---------------------------------------------------------------------------
__global__ void __launch_bounds__(256) k_partial(const float* __restrict__ logits)
{
    const int row = blockIdx.x >> 3;
    const int blk = blockIdx.x & 7;
    const int t   = threadIdx.x;
    const unsigned F = 0xffffffffu;
    const float* __restrict__ x = logits + (size_t)row * VOCAB;

    const int base = blk * BLOCK_ELEMS;
    const int end  = min(base + BLOCK_ELEMS, VOCAB);

    // 4 independent branchless LSE accumulators
    float m0 = NEG_INF, m1 = NEG_INF, m2 = NEG_INF, m3 = NEG_INF;
    float s0 = 0.f, s1 = 0.f, s2 = 0.f, s3 = 0.f;
    float lv[TOPK]; int li[TOPK];
#pragma unroll
    for (int j = 0; j < TOPK; j++) { lv[j] = NEG_INF; li[j] = IDX_MAX; }

#pragma unroll 1
    for (int i = base + t; i < end; i += 1024) {
        const int i1 = i + 256, i2 = i + 512, i3 = i + 768;
        float v0 = x[i];
        float v1 = (i1 < end) ? x[i1] : NEG_INF;
        float v2 = (i2 < end) ? x[i2] : NEG_INF;
        float v3 = (i3 < end) ? x[i3] : NEG_INF;

        { float nm = fmaxf(m0, v0); s0 = s0 * __expf(m0 - nm) + __expf(v0 - nm); m0 = nm; }
        if (i1 < end) { float nm = fmaxf(m1, v1); s1 = s1 * __expf(m1 - nm) + __expf(v1 - nm); m1 = nm; }
        if (i2 < end) { float nm = fmaxf(m2, v2); s2 = s2 * __expf(m2 - nm) + __expf(v2 - nm); m2 = nm; }
        if (i3 < end) { float nm = fmaxf(m3, v3); s3 = s3 * __expf(m3 - nm) + __expf(v3 - nm); m3 = nm; }

        top8_insert(v0, i, lv, li);
        if (i1 < end) top8_insert(v1, i1, lv, li);
        if (i2 < end) top8_insert(v2, i2, lv, li);
        if (i3 < end) top8_insert(v3, i3, lv, li);
    }

    // merge the 4 accumulators (all real: every thread sees >= 21 elements)
    float m = m0, s = s0;
    { float nm = fmaxf(m, m1); s = s * __expf(m - nm) + s1 * __expf(m1 - nm); m = nm; }
    { float nm = fmaxf(m, m2); s = s * __expf(m - nm) + s2 * __expf(m2 - nm); m = nm; }
    { float nm = fmaxf(m, m3); s = s * __expf(m - nm) + s3 * __expf(m3 - nm); m = nm; }

    // warp LSE reduce
    for (int off = 16; off; off >>= 1) {
        float om = __shfl_xor_sync(F, m, off);
        float os = __shfl_xor_sync(F, s, off);
        float nm = fmaxf(m, om);
        s = s * __expf(m - nm) + os * __expf(om - nm);
        m = nm;
    }

    __shared__ float sm_m[8], sm_s[8];
    __shared__ float s_wv[8][TOPK];
    __shared__ int   s_wi[8][TOPK];
    const int wid = t >> 5, lane = t & 31;
    if (lane == 0) { sm_m[wid] = m; sm_s[wid] = s; }

    // per-warp top-8
    warp_top8_merge(lv, li, TOPK, s_wv[wid], s_wi[wid]);
    __syncthreads();

    // warp 0: merge 8 warps x 8 = 64 candidates -> block top-8; reduce LSE partials
    if (wid == 0) {
        float cv[2]; int ci[2];
        const int f0 = lane, f1 = lane + 32;
        float a = s_wv[f0 >> 3][f0 & 7]; int ai = s_wi[f0 >> 3][f0 & 7];
        float b = s_wv[f1 >> 3][f1 & 7]; int bi = s_wi[f1 >> 3][f1 & 7];
        if (b > a || (b == a && bi < ai)) { cv[0] = b; ci[0] = bi; cv[1] = a; ci[1] = ai; }
        else                             { cv[0] = a; ci[0] = ai; cv[1] = b; ci[1] = bi; }

        float ov[TOPK]; int oi[TOPK];
        // reuse warp merge with depth 2
        float l2[TOPK]; int i2_[TOPK];
#pragma unroll
        for (int j = 0; j < TOPK; j++) { l2[j] = (j < 2) ? cv[j] : NEG_INF; i2_[j] = (j < 2) ? ci[j] : IDX_MAX; }
        warp_top8_merge(l2, i2_, 2, ov, oi);

        if (lane == 0) {
            float M = sm_m[0], S = sm_s[0];
#pragma unroll
            for (int w = 1; w < 8; w++) {
                float nm = fmaxf(M, sm_m[w]);
                S = S * __expf(M - nm) + sm_s[w] * __expf(sm_m[w] - nm);
                M = nm;
            }
            g_blk_m[row][blk] = M;
            g_blk_s[row][blk] = S;
#pragma unroll
            for (int j = 0; j < TOPK; j++) {
                g_blk_topv[row][blk * TOPK + j] = ov[j];
                g_blk_topi[row][blk * TOPK + j] = oi[j];
            }
        }
    }
}

// ---------------------------------------------------------------------------
// Kernel 2: per-row merge (8 blocks) + LSE combine + beam selection + outputs.
// 1 block, 256 threads.
// ---------------------------------------------------------------------------
__global__ void __launch_bounds__(256) k_merge_select(const float* __restrict__ prev,
                                                      const int*   __restrict__ save_id,
                                                      float*       __restrict__ out)
{
    const int t = threadIdx.x;
    const int wid = t >> 5, lane = t & 31;
    const unsigned F = 0xffffffffu;

    __shared__ float s_topv[BEAM][TOPK];
    __shared__ int   s_topi[BEAM][TOPK];
    __shared__ float s_lse[BEAM];
    __shared__ int   s_beam[BEAM], s_tok[BEAM];
    __shared__ float s_prob[BEAM];

    // warp r: merge row r's 64 candidates (2/lane) + combine LSE
    {
        const int row = wid;
        const int f0 = lane, f1 = lane + 32;
        float a = g_blk_topv[row][f0]; int ai = g_blk_topi[row][f0];
        float b = g_blk_topv[row][f1]; int bi = g_blk_topi[row][f1];
        float l2[TOPK]; int i2_[TOPK];
        if (b > a || (b == a && bi < ai)) { l2[0] = b; i2_[0] = bi; l2[1] = a; i2_[1] = ai; }
        else                              { l2[0] = a; i2_[0] = ai; l2[1] = b; i2_[1] = bi; }
#pragma unroll
        for (int j = 2; j < TOPK; j++) { l2[j] = NEG_INF; i2_[j] = IDX_MAX; }
        warp_top8_merge(l2, i2_, 2, s_topv[row], s_topi[row]);

        if (lane == 0) {
            float M = g_blk_m[row][0], S = g_blk_s[row][0];
#pragma unroll
            for (int w = 1; w < BLKS_PER_ROW; w++) {
                float om = g_blk_m[row][w], os = g_blk_s[row][w];
                float nm = fmaxf(M, om);
                S = S * __expf(M - nm) + os * __expf(om - nm);
                M = nm;
            }
            s_lse[row] = M + logf(S);
        }
    }
    __syncthreads();

    // warp 0: beam selection over 64 (row-major) candidates, tie -> smaller flat index
    if (wid == 0) {
        const int f0 = lane, f1 = lane + 32;
        float v0 = s_topv[f0 >> 3][f0 & 7] - s_lse[f0 >> 3] + prev[f0 >> 3];
        float v1 = s_topv[f1 >> 3][f1 & 7] - s_lse[f1 >> 3] + prev[f1 >> 3];
        float c0v, c1v; int c0i, c1i;
        if (v1 > v0) { c0v = v1; c0i = f1; c1v = v0; c1i = f0; }
        else         { c0v = v0; c0i = f0; c1v = v1; c1i = f1; }

        int ptr = 0;
#pragma unroll
        for (int r = 0; r < BEAM; r++) {
            float rv; int ri;
            if      (ptr == 0) { rv = c0v; ri = c0i; }
            else if (ptr == 1) { rv = c1v; ri = c1i; }
            else               { rv = NEG_INF; ri = IDX_MAX; }
            int rl = lane;
            for (int off = 16; off; off >>= 1) {
                float ov = __shfl_xor_sync(F, rv, off);
                int   oi = __shfl_xor_sync(F, ri, off);
                int   ol = __shfl_xor_sync(F, rl, off);
                if (ov > rv || (ov == rv && oi < ri)) { rv = ov; ri = oi; rl = ol; }
            }
            if (lane == rl) ptr++;
            if (lane == 0) {
                const int beam = ri >> 3;
                s_beam[r] = beam;
                s_tok[r]  = s_topi[beam][ri & 7];
                s_prob[r] = rv;
            }
        }
    }
    __syncthreads();

    const size_t OFF = KV_ELEMS;
    // new_save_id (8 x 129), all 256 threads
    for (int e = t; e < BEAM * (HIST + 1); e += 256) {
        const int r = e / (HIST + 1), c = e % (HIST + 1);
        out[OFF + e] = (c < HIST) ? (float)save_id[s_beam[r] * HIST + c]
                                  : (float)s_tok[r];
    }
    if (t < BEAM) {
        out[OFF + 1032 + t] = s_prob[t];         // top_beam_prob (8,1)
        out[OFF + 1040 + t] = (float)s_tok[t];   // tbi (8,1)
        g_beam_index[t] = s_beam[t];
    }
    if (t == 0)
        out[OFF + 1048] = (float)s_tok[0];       // max_logits_idx (1,1)
}

// ---------------------------------------------------------------------------
// Kernel 3: kv gather. Beam innermost in block order so duplicate-beam reads
// of the same (layer, chunk) hit L2 back-to-back.
// ---------------------------------------------------------------------------
__global__ void __launch_bounds__(256) k_gather(const float4* __restrict__ src,
                                                float4*       __restrict__ dst)
{
    const int b     = blockIdx.x & 7;
    const int chunk = (blockIdx.x >> 3) & 63;
    const int l     = blockIdx.x >> 9;
    const int slab      = (l << 3) | b;
    const int src_slab  = (l << 3) | g_beam_index[b];

    const size_t out_base = ((size_t)slab     << SLAB_F4_SHIFT) + ((size_t)chunk << 12);
    const size_t in_base  = ((size_t)src_slab << SLAB_F4_SHIFT) + ((size_t)chunk << 12);

#pragma unroll
    for (int k = 0; k < 16; k++) {
        const int off = threadIdx.x + k * 256;
        dst[out_base + off] = src[in_base + off];
    }
}

// ---------------------------------------------------------------------------
extern "C" void kernel_launch(void* const* d_in, const int* in_sizes, int n_in,
                              void* d_out, int out_size)
{
    const float* kv      = (const float*)d_in[0];
    const float* logits  = (const float*)d_in[1];
    const int*   save_id = (const int*)  d_in[2];
    const float* prev    = (const float*)d_in[3];
    float* out = (float*)d_out;

    k_partial<<<BEAM * BLKS_PER_ROW, 256>>>(logits);
    k_merge_select<<<1, 256>>>(prev, save_id, out);
    k_gather<<<16384, 256>>>((const float4*)kv, (float4*)out);
}